// round 17
// baseline (speedup 1.0000x reference)
#include <cuda_runtime.h>
#include <cstdint>

#define BB 1024
#define TT 2048
#define DD 16
#define UU 4
#define HH 128
#define MM 8            // rows per tile
#define MROWS 16        // rows per CTA (2 tiles)
#define NT 256
#define PIT 24          // row pitch (floats): cols 0-7 tile A, 8-15 tile B
#define PPIT 10         // sPart row pitch

typedef unsigned long long u64;

__device__ __forceinline__ uint32_t tf32r(float v) {
    uint32_t r; asm("cvt.rna.tf32.f32 %0, %1;" : "=r"(r) : "f"(v)); return r;
}
__device__ __forceinline__ float tanh_fast(float x) {
    float y; asm("tanh.approx.f32 %0, %1;" : "=f"(y) : "f"(x)); return y;
}
__device__ __forceinline__ void mma8(float* d, uint4 a, uint32_t b0, uint32_t b1) {
    asm volatile(
        "mma.sync.aligned.m16n8k8.row.col.f32.tf32.tf32.f32 "
        "{%0,%1,%2,%3}, {%4,%5,%6,%7}, {%8,%9}, {%0,%1,%2,%3};"
        : "+f"(d[0]), "+f"(d[1]), "+f"(d[2]), "+f"(d[3])
        : "r"(a.x), "r"(a.y), "r"(a.z), "r"(a.w), "r"(b0), "r"(b1));
}
__device__ __forceinline__ u64 pku(uint32_t lo, uint32_t hi) {
    return ((u64)hi << 32) | (u64)lo;
}

__global__ void __launch_bounds__(NT, 1)
gnsde_kernel(const float* __restrict__ carry,
             const float* __restrict__ x,
             const float* __restrict__ noise,
             const float* __restrict__ W0,
             const float* __restrict__ b0,
             const float* __restrict__ W1,
             const float* __restrict__ b1,
             const float* __restrict__ W2,
             const float* __restrict__ b2,
             float* __restrict__ out)
{
    __shared__ __align__(16) float sIN[DD * PIT];      // y rows; cols 0-7 A, 8-15 B
    __shared__ __align__(16) float sX[MROWS * 4];      // x_t fp32; m 0-7 A, 8-15 B
    __shared__ __align__(16) float sH1[HH * PIT];
    __shared__ __align__(16) float sH2[HH * PIT];
    __shared__ __align__(16) float sPartA[8 * 16 * PPIT];
    __shared__ __align__(16) float sPartB[8 * 16 * PPIT];

    const int tid  = threadIdx.x;
    const int wid  = tid >> 5;
    const int lane = tid & 31;
    const int g    = lane >> 2;      // groupID
    const int tg   = lane & 3;       // threadID_in_group
    const int b0r  = blockIdx.x * MROWS;

    const int r0 = wid * 16 + g;     // A-fragment rows (j / d)
    const int r1 = r0 + 8;

    // ---- persistent weight fragments (1-term tf32), SHARED across both tiles ----
    uint4 A1h[16];
#pragma unroll
    for (int c = 0; c < 16; ++c) {
        int k0 = 8 * c + tg, k1 = k0 + 4;
        A1h[c].x = tf32r(W1[k0 * HH + r0]);
        A1h[c].y = tf32r(W1[k0 * HH + r1]);
        A1h[c].z = tf32r(W1[k1 * HH + r0]);
        A1h[c].w = tf32r(W1[k1 * HH + r1]);
    }
    uint4 A0h[2];
#pragma unroll
    for (int c = 0; c < 2; ++c) {
        int k0 = 8 * c + tg, k1 = k0 + 4;
        A0h[c].x = tf32r(W0[k0 * HH + r0]);
        A0h[c].y = tf32r(W0[k0 * HH + r1]);
        A0h[c].z = tf32r(W0[k1 * HH + r0]);
        A0h[c].w = tf32r(W0[k1 * HH + r1]);
    }
    float w0xA[UU], w0xB[UU];        // W0 x-rows, fp32 exact (rows r0/r1)
#pragma unroll
    for (int u = 0; u < UU; ++u) {
        w0xA[u] = W0[(DD + u) * HH + r0];
        w0xB[u] = W0[(DD + u) * HH + r1];
    }
    uint4 A2h[2];
#pragma unroll
    for (int i = 0; i < 2; ++i) {
        int c = 2 * wid + i;
        int k0 = 8 * c + tg, k1 = k0 + 4;
        A2h[i].x = tf32r(W2[k0 * DD + g]);
        A2h[i].y = tf32r(W2[k0 * DD + g + 8]);
        A2h[i].z = tf32r(W2[k1 * DD + g]);
        A2h[i].w = tf32r(W2[k1 * DD + g + 8]);
    }
    const float b0a = b0[r0], b0b = b0[r1];
    const float b1a = b1[r0], b1b = b1[r1];

    // gate identity (tid < 128): m = tid>>4 (within tile), d = tid&15
    const int mR = tid >> 4;
    const int dR = tid & 15;
    const float b2v = b2[dR];
    float yregA = 0.0f, yregB = 0.0f;

    uint32_t* sINu = (uint32_t*)sIN;
    uint32_t* sH1u = (uint32_t*)sH1;
    uint32_t* sH2u = (uint32_t*)sH2;
    if (tid < 128) {
        yregA = carry[(size_t)(b0r + mR) * DD + dR];
        yregB = carry[(size_t)(b0r + 8 + mR) * DD + dR];
        sINu[dR * PIT + mR]     = tf32r(yregA);
        sINu[dR * PIT + 8 + mR] = tf32r(yregB);
    }
    if (tid >= 128 && tid < 128 + MROWS) {
        int m = tid & 15;
        float4 xv = *(const float4*)&x[((size_t)(b0r + m) * TT) * UU];
        *(float4*)&sX[m * 4] = xv;
    }

    const float alpha = 0.1f;
    const float onema = 0.9f;
    const float sqa   = 0.31622776601683794f;

    for (int t = 0; t < TT; ++t) {
        // ---- prefetch globals ----
        float nzA = 0.0f, nzB = 0.0f;
        if (tid < 128) {
            nzA = noise[((size_t)(b0r + mR) * TT + t) * DD + dR];
            nzB = noise[((size_t)(b0r + 8 + mR) * TT + t) * DD + dR];
        }
        float4 xn = make_float4(0.f, 0.f, 0.f, 0.f);
        const bool xp = (tid >= 128 && tid < 128 + MROWS) && (t + 1 < TT);
        if (xp) xn = *(const float4*)&x[((size_t)(b0r + (tid & 15)) * TT + (t + 1)) * UU];

        __syncthreads();   // (1)

        // ===== layer 0: both tiles, 2 chains each + fp32 x-fold =====
        {
            float PA0[4] = {0, 0, 0, 0}, PA1[4] = {0, 0, 0, 0};
            float PB0[4] = {0, 0, 0, 0}, PB1[4] = {0, 0, 0, 0};
            {
                uint32_t a0 = sINu[tg * PIT + g];
                uint32_t a1 = sINu[(tg + 4) * PIT + g];
                uint32_t a2 = sINu[(8 + tg) * PIT + g];
                uint32_t a3 = sINu[(12 + tg) * PIT + g];
                uint32_t e0 = sINu[tg * PIT + 8 + g];
                uint32_t e1 = sINu[(tg + 4) * PIT + 8 + g];
                uint32_t e2 = sINu[(8 + tg) * PIT + 8 + g];
                uint32_t e3 = sINu[(12 + tg) * PIT + 8 + g];
                mma8(PA0, A0h[0], a0, a1);
                mma8(PB0, A0h[0], e0, e1);
                mma8(PA1, A0h[1], a2, a3);
                mma8(PB1, A0h[1], e2, e3);
            }
            float4 xaA = *(const float4*)&sX[(2 * tg) * 4];
            float4 xbA = *(const float4*)&sX[(2 * tg + 1) * 4];
            float4 xaB = *(const float4*)&sX[(8 + 2 * tg) * 4];
            float4 xbB = *(const float4*)&sX[(8 + 2 * tg + 1) * 4];
            float sA0 = w0xA[0] * xaA.x + w0xA[1] * xaA.y + w0xA[2] * xaA.z + w0xA[3] * xaA.w;
            float sA1 = w0xA[0] * xbA.x + w0xA[1] * xbA.y + w0xA[2] * xbA.z + w0xA[3] * xbA.w;
            float sA2 = w0xB[0] * xaA.x + w0xB[1] * xaA.y + w0xB[2] * xaA.z + w0xB[3] * xaA.w;
            float sA3 = w0xB[0] * xbA.x + w0xB[1] * xbA.y + w0xB[2] * xbA.z + w0xB[3] * xbA.w;
            float sB0 = w0xA[0] * xaB.x + w0xA[1] * xaB.y + w0xA[2] * xaB.z + w0xA[3] * xaB.w;
            float sB1 = w0xA[0] * xbB.x + w0xA[1] * xbB.y + w0xA[2] * xbB.z + w0xA[3] * xbB.w;
            float sB2 = w0xB[0] * xaB.x + w0xB[1] * xaB.y + w0xB[2] * xaB.z + w0xB[3] * xaB.w;
            float sB3 = w0xB[0] * xbB.x + w0xB[1] * xbB.y + w0xB[2] * xbB.z + w0xB[3] * xbB.w;
            float hA0 = tanh_fast((PA0[0] + PA1[0]) + sA0 + b0a);
            float hA1 = tanh_fast((PA0[1] + PA1[1]) + sA1 + b0a);
            float hA2 = tanh_fast((PA0[2] + PA1[2]) + sA2 + b0b);
            float hA3 = tanh_fast((PA0[3] + PA1[3]) + sA3 + b0b);
            float hB0 = tanh_fast((PB0[0] + PB1[0]) + sB0 + b0a);
            float hB1 = tanh_fast((PB0[1] + PB1[1]) + sB1 + b0a);
            float hB2 = tanh_fast((PB0[2] + PB1[2]) + sB2 + b0b);
            float hB3 = tanh_fast((PB0[3] + PB1[3]) + sB3 + b0b);
            *(u64*)&sH1u[r0 * PIT + 2 * tg]     = pku(tf32r(hA0), tf32r(hA1));
            *(u64*)&sH1u[r1 * PIT + 2 * tg]     = pku(tf32r(hA2), tf32r(hA3));
            *(u64*)&sH1u[r0 * PIT + 8 + 2 * tg] = pku(tf32r(hB0), tf32r(hB1));
            *(u64*)&sH1u[r1 * PIT + 8 + 2 * tg] = pku(tf32r(hB2), tf32r(hB3));
        }
        __syncthreads();   // (2)

        // ===== layer 1: K=128, 16 chunks; 4 chains per tile =====
        {
            float PA0[4] = {0,0,0,0}, PA1[4] = {0,0,0,0}, PA2[4] = {0,0,0,0}, PA3[4] = {0,0,0,0};
            float PB0[4] = {0,0,0,0}, PB1[4] = {0,0,0,0}, PB2[4] = {0,0,0,0}, PB3[4] = {0,0,0,0};
#pragma unroll
            for (int q = 0; q < 4; ++q) {
                int cb = 4 * q;
                int rr0 = 8 * (cb + 0) + tg;
                int rr1 = 8 * (cb + 1) + tg;
                int rr2 = 8 * (cb + 2) + tg;
                int rr3 = 8 * (cb + 3) + tg;
                uint32_t a00 = sH1u[rr0 * PIT + g], a01 = sH1u[(rr0 + 4) * PIT + g];
                uint32_t a10 = sH1u[rr1 * PIT + g], a11 = sH1u[(rr1 + 4) * PIT + g];
                uint32_t a20 = sH1u[rr2 * PIT + g], a21 = sH1u[(rr2 + 4) * PIT + g];
                uint32_t a30 = sH1u[rr3 * PIT + g], a31 = sH1u[(rr3 + 4) * PIT + g];
                uint32_t e00 = sH1u[rr0 * PIT + 8 + g], e01 = sH1u[(rr0 + 4) * PIT + 8 + g];
                uint32_t e10 = sH1u[rr1 * PIT + 8 + g], e11 = sH1u[(rr1 + 4) * PIT + 8 + g];
                uint32_t e20 = sH1u[rr2 * PIT + 8 + g], e21 = sH1u[(rr2 + 4) * PIT + 8 + g];
                uint32_t e30 = sH1u[rr3 * PIT + 8 + g], e31 = sH1u[(rr3 + 4) * PIT + 8 + g];
                mma8(PA0, A1h[cb + 0], a00, a01);
                mma8(PB0, A1h[cb + 0], e00, e01);
                mma8(PA1, A1h[cb + 1], a10, a11);
                mma8(PB1, A1h[cb + 1], e10, e11);
                mma8(PA2, A1h[cb + 2], a20, a21);
                mma8(PB2, A1h[cb + 2], e20, e21);
                mma8(PA3, A1h[cb + 3], a30, a31);
                mma8(PB3, A1h[cb + 3], e30, e31);
            }
            float hA0 = tanh_fast(((PA0[0] + PA1[0]) + (PA2[0] + PA3[0])) + b1a);
            float hA1 = tanh_fast(((PA0[1] + PA1[1]) + (PA2[1] + PA3[1])) + b1a);
            float hA2 = tanh_fast(((PA0[2] + PA1[2]) + (PA2[2] + PA3[2])) + b1b);
            float hA3 = tanh_fast(((PA0[3] + PA1[3]) + (PA2[3] + PA3[3])) + b1b);
            float hB0 = tanh_fast(((PB0[0] + PB1[0]) + (PB2[0] + PB3[0])) + b1a);
            float hB1 = tanh_fast(((PB0[1] + PB1[1]) + (PB2[1] + PB3[1])) + b1a);
            float hB2 = tanh_fast(((PB0[2] + PB1[2]) + (PB2[2] + PB3[2])) + b1b);
            float hB3 = tanh_fast(((PB0[3] + PB1[3]) + (PB2[3] + PB3[3])) + b1b);
            *(u64*)&sH2u[r0 * PIT + 2 * tg]     = pku(tf32r(hA0), tf32r(hA1));
            *(u64*)&sH2u[r1 * PIT + 2 * tg]     = pku(tf32r(hA2), tf32r(hA3));
            *(u64*)&sH2u[r0 * PIT + 8 + 2 * tg] = pku(tf32r(hB0), tf32r(hB1));
            *(u64*)&sH2u[r1 * PIT + 8 + 2 * tg] = pku(tf32r(hB2), tf32r(hB3));
        }
        __syncthreads();   // (3)

        // ===== layer 2: k-split across warps, both tiles =====
        {
            float PA0[4] = {0,0,0,0}, PA1[4] = {0,0,0,0};
            float PB0[4] = {0,0,0,0}, PB1[4] = {0,0,0,0};
            {
                int rA = 8 * (2 * wid) + tg;
                int rB = 8 * (2 * wid + 1) + tg;
                uint32_t a0 = sH2u[rA * PIT + g],     a1 = sH2u[(rA + 4) * PIT + g];
                uint32_t c0 = sH2u[rB * PIT + g],     c1 = sH2u[(rB + 4) * PIT + g];
                uint32_t e0 = sH2u[rA * PIT + 8 + g], e1 = sH2u[(rA + 4) * PIT + 8 + g];
                uint32_t f0 = sH2u[rB * PIT + 8 + g], f1 = sH2u[(rB + 4) * PIT + 8 + g];
                mma8(PA0, A2h[0], a0, a1);
                mma8(PB0, A2h[0], e0, e1);
                mma8(PA1, A2h[1], c0, c1);
                mma8(PB1, A2h[1], f0, f1);
            }
            *(float2*)&sPartA[wid * 160 + g * PPIT + 2 * tg] =
                make_float2(PA0[0] + PA1[0], PA0[1] + PA1[1]);
            *(float2*)&sPartA[wid * 160 + (g + 8) * PPIT + 2 * tg] =
                make_float2(PA0[2] + PA1[2], PA0[3] + PA1[3]);
            *(float2*)&sPartB[wid * 160 + g * PPIT + 2 * tg] =
                make_float2(PB0[0] + PB1[0], PB0[1] + PB1[1]);
            *(float2*)&sPartB[wid * 160 + (g + 8) * PPIT + 2 * tg] =
                make_float2(PB0[2] + PB1[2], PB0[3] + PB1[3]);
        }

        // (4) asymmetric: warps 0-3 sync + reduce/gate; warps 4-7 arrive + stage x
        if (wid < 4) {
            asm volatile("bar.sync 1, %0;" :: "n"(NT) : "memory");
            float sA = 0.0f, sB = 0.0f;
#pragma unroll
            for (int w = 0; w < 8; ++w) {
                sA += sPartA[w * 160 + dR * PPIT + mR];
                sB += sPartB[w * 160 + dR * PPIT + mR];
            }
            float mtA = sA + b2v;
            float muA = onema * yregA + alpha * mtA;
            float ynA = muA + sqa * nzA;
            float mtB = sB + b2v;
            float muB = onema * yregB + alpha * mtB;
            float ynB = muB + sqa * nzB;
            yregA = ynA; yregB = ynB;
            sINu[dR * PIT + mR]     = tf32r(ynA);   // publish state first
            sINu[dR * PIT + 8 + mR] = tf32r(ynB);
            size_t baseA = ((size_t)(b0r + mR) * TT + t) * DD + dR;
            size_t baseB = ((size_t)(b0r + 8 + mR) * TT + t) * DD + dR;
            out[baseA]                        = ynA;
            out[baseA + (size_t)BB * TT * DD] = mtA;
            out[baseA + 2ull * BB * TT * DD]  = muA;
            out[baseB]                        = ynB;
            out[baseB + (size_t)BB * TT * DD] = mtB;
            out[baseB + 2ull * BB * TT * DD]  = muB;
        } else {
            asm volatile("bar.arrive 1, %0;" :: "n"(NT) : "memory");
            if (xp) {
                int m = tid & 15;
                *(float4*)&sX[m * 4] = xn;
            }
        }
    }
}

extern "C" void kernel_launch(void* const* d_in, const int* in_sizes, int n_in,
                              void* d_out, int out_size) {
    const float* carry = (const float*)d_in[0];
    const float* x     = (const float*)d_in[1];
    const float* noise = (const float*)d_in[2];
    const float* W0    = (const float*)d_in[3];
    const float* b0    = (const float*)d_in[4];
    const float* W1    = (const float*)d_in[5];
    const float* b1    = (const float*)d_in[6];
    const float* W2    = (const float*)d_in[7];
    const float* b2    = (const float*)d_in[8];
    float* out = (float*)d_out;

    gnsde_kernel<<<BB / MROWS, NT>>>(carry, x, noise, W0, b0, W1, b1, W2, b2, out);
}